// round 5
// baseline (speedup 1.0000x reference)
#include <cuda_runtime.h>

#define SEQ 2048
#define BATCH 1024
#define NL 6
#define UF 8
#define MASK 0xFFFFFFFFu   // all 32 lanes resident -> no convergence sync on shfl

__device__ __forceinline__ float tanh_ap(float x) {
    float y;
    asm("tanh.approx.f32 %0, %1;" : "=f"(y) : "f"(x));
    return y;
}
// Predicated store. NOTE: no "memory" clobber — out is written only here,
// and volatile keeps emission/ordering among these stores. This avoids a
// full compiler scheduling fence every tick.
__device__ __forceinline__ void store_pred(int flag, float* p, float v) {
    asm volatile(
        "{\n\t.reg .pred %%pp;\n\t"
        "setp.ne.s32 %%pp, %0, 0;\n\t"
        "@%%pp st.global.f32 [%1], %2;\n\t}"
        :: "r"(flag), "l"(p), "f"(v));
}

struct LaneState {
    float wih[4][4], whh[4][4], bias[4];
    float h, c;                  // h holds 2*h_true (feeder lanes: raw x)
    float rw0, rw1, rw2, rw3, rb;
    int l, bh, bi, b;
    int isfeed, headflag;
};

template<bool Guarded>
__device__ __forceinline__ void tick(int k, LaneState& s, float& xslot,
                                     const float* __restrict__ xptr,
                                     float* __restrict__ out)
{
    // Cross-lane h (values are 2h; weights pre-halved). Full mask, no sync.
    const float hv0 = __shfl_sync(MASK, s.h, s.bh + 0);
    const float hv1 = __shfl_sync(MASK, s.h, s.bh + 1);
    const float hv2 = __shfl_sync(MASK, s.h, s.bh + 2);
    const float hv3 = __shfl_sync(MASK, s.h, s.bh + 3);
    const float iv0 = __shfl_sync(MASK, s.h, s.bi + 0);
    const float iv1 = __shfl_sync(MASK, s.h, s.bi + 1);
    const float iv2 = __shfl_sync(MASK, s.h, s.bi + 2);
    const float iv3 = __shfl_sync(MASK, s.h, s.bi + 3);

    // Linear head (rw pre-scaled by 0.5 since hv = 2h).
    float y = s.rb;
    y = fmaf(s.rw0, hv0, y);
    y = fmaf(s.rw1, hv1, y);
    y = fmaf(s.rw2, hv2, y);
    y = fmaf(s.rw3, hv3, y);
    const int t_out = k - NL;
    const int t_ok = Guarded ? ((unsigned)t_out < SEQ) : 1;
    const int t_cl = Guarded ? (t_out < 0 ? 0 : (t_out >= SEQ ? SEQ - 1 : t_out)) : t_out;
    store_pred(s.headflag & t_ok, out + (size_t)t_cl * BATCH + s.b, y);

    // Two parallel 4-FMA chains per gate (iv-chain with bias, hv-chain from mul).
    float a0 = s.bias[0], a1 = s.bias[1], a2 = s.bias[2], a3 = s.bias[3];
    float p0, p1, p2, p3;
    a0 = fmaf(s.wih[0][0], iv0, a0); p0 = s.whh[0][0] * hv0;
    a1 = fmaf(s.wih[1][0], iv0, a1); p1 = s.whh[1][0] * hv0;
    a2 = fmaf(s.wih[2][0], iv0, a2); p2 = s.whh[2][0] * hv0;
    a3 = fmaf(s.wih[3][0], iv0, a3); p3 = s.whh[3][0] * hv0;

    a0 = fmaf(s.wih[0][1], iv1, a0); p0 = fmaf(s.whh[0][1], hv1, p0);
    a1 = fmaf(s.wih[1][1], iv1, a1); p1 = fmaf(s.whh[1][1], hv1, p1);
    a2 = fmaf(s.wih[2][1], iv1, a2); p2 = fmaf(s.whh[2][1], hv1, p2);
    a3 = fmaf(s.wih[3][1], iv1, a3); p3 = fmaf(s.whh[3][1], hv1, p3);

    a0 = fmaf(s.wih[0][2], iv2, a0); p0 = fmaf(s.whh[0][2], hv2, p0);
    a1 = fmaf(s.wih[1][2], iv2, a1); p1 = fmaf(s.whh[1][2], hv2, p1);
    a2 = fmaf(s.wih[2][2], iv2, a2); p2 = fmaf(s.whh[2][2], hv2, p2);
    a3 = fmaf(s.wih[3][2], iv2, a3); p3 = fmaf(s.whh[3][2], hv2, p3);

    a0 = fmaf(s.wih[0][3], iv3, a0); p0 = fmaf(s.whh[0][3], hv3, p0);
    a1 = fmaf(s.wih[1][3], iv3, a1); p1 = fmaf(s.whh[1][3], hv3, p1);
    a2 = fmaf(s.wih[2][3], iv3, a2); p2 = fmaf(s.whh[2][3], hv3, p2);
    a3 = fmaf(s.wih[3][3], iv3, a3); p3 = fmaf(s.whh[3][3], hv3, p3);

    // Gates: i,f,o pre-scaled by 0.5 (sigmoid-as-tanh fold); g unscaled.
    const float ti = tanh_ap(a0 + p0);
    const float tf = tanh_ap(a1 + p1);
    const float cc = tanh_ap(a2 + p2);
    const float to = tanh_ap(a3 + p3);

    // c_new = 0.5*(tf*c + c) + 0.5*(ti*cc + cc); th = tanh(c_new) directly.
    const float u  = fmaf(tf, s.c, s.c);
    const float w  = 0.5f * fmaf(ti, cc, cc);
    const float nc = fmaf(0.5f, u, w);
    const float th = tanh_ap(nc);
    const float nh = fmaf(to, th, th);          // 2*h_new

    const float xv = xslot;
    xslot = __ldg(xptr);

    if (Guarded) {
        const int valid = ((unsigned)(k - s.l) < SEQ);
        const float nh2 = valid ? nh : s.h;
        const float nc2 = valid ? nc : s.c;
        s.h = s.isfeed ? xv : nh2;
        s.c = s.isfeed ? s.c : nc2;
    } else {
        s.h = s.isfeed ? xv : nh;
        s.c = nc;   // feeder's c is inert; harmless
    }
}

__global__ __launch_bounds__(32) void lstm_reg_kernel(
    const float* __restrict__ x,      // [S, B, 4]
    const float* __restrict__ w_ih,   // [6, 16, 4]
    const float* __restrict__ w_hh,   // [6, 16, 4]
    const float* __restrict__ b_ih,   // [6, 16]
    const float* __restrict__ b_hh,   // [6, 16]
    const float* __restrict__ reg_w,  // [1, 4]
    const float* __restrict__ reg_b,  // [1]
    float* __restrict__ out)          // [S, B, 1]
{
    const int lane = threadIdx.x & 31;

    LaneState s;
    s.b = blockIdx.x;                    // one warp (block) per batch element
    s.l = lane >> 2;                     // 0..5 layers; 6,7 = feeder duplicates
    const int j = lane & 3;
    s.bh = s.l * 4;
    s.bi = (s.l == 0) ? 24 : ((s.l - 1) & 7) * 4;
    s.isfeed = (s.l >= 6);
    s.headflag = (lane == 20);

#pragma unroll
    for (int g = 0; g < 4; ++g) {
#pragma unroll
        for (int i = 0; i < 4; ++i) { s.wih[g][i] = 0.f; s.whh[g][i] = 0.f; }
        s.bias[g] = 0.f;
    }
    if (s.l < 6) {
#pragma unroll
        for (int g = 0; g < 4; ++g) {
            const int row = s.l * 16 + g * 4 + j;       // gate order i,f,g,o
            const float gsc = (g == 2) ? 1.0f : 0.5f;   // sigmoid-as-tanh fold
            const float isc = (s.l == 0) ? 1.0f : 0.5f; // input is 2h for layers>0
#pragma unroll
            for (int i = 0; i < 4; ++i) {
                s.wih[g][i] = w_ih[row * 4 + i] * gsc * isc;
                s.whh[g][i] = w_hh[row * 4 + i] * gsc * 0.5f;  // own h is 2h
            }
            s.bias[g] = (b_ih[row] + b_hh[row]) * gsc;
        }
    }
    s.rw0 = reg_w[0] * 0.5f; s.rw1 = reg_w[1] * 0.5f;
    s.rw2 = reg_w[2] * 0.5f; s.rw3 = reg_w[3] * 0.5f;
    s.rb  = reg_b[0];

    s.h = 0.f; s.c = 0.f;
    const float* xq = x + (size_t)s.b * 4 + j;
    if (s.isfeed) s.h = xq[0];           // feeder starts with x[0] (raw x)

    // Prefetch ring: slot u holds x[tick+1] for tick ≡ u (mod UF).
    float xbuf[UF];
#pragma unroll
    for (int u = 0; u < UF; ++u) {
        const int idx = (u + 1 < SEQ) ? (u + 1) : (SEQ - 1);
        xbuf[u] = xq[(size_t)idx * BATCH * 4];
    }

    // ---- fill: ticks 0..7 (guarded) ----
#pragma unroll
    for (int u = 0; u < UF; ++u) {
        const int k = u;
        const int pidx = (k + 1 + UF < SEQ) ? (k + 1 + UF) : (SEQ - 1);
        tick<true>(k, s, xbuf[u], xq + (size_t)pidx * BATCH * 4, out);
    }

    // ---- main: ticks 8..2031, guard-free ----
#pragma unroll 1
    for (int kc = UF; kc < 2032; kc += UF) {
        const float* xb = xq + (size_t)(kc + 1 + UF) * BATCH * 4;
#pragma unroll
        for (int u = 0; u < UF; ++u)
            tick<false>(kc + u, s, xbuf[u], xb + (size_t)u * BATCH * 4, out);
    }

    // ---- drain: ticks 2032..2055 (guarded) ----
#pragma unroll 1
    for (int kc = 2032; kc < 2032 + 3 * UF; kc += UF) {
#pragma unroll
        for (int u = 0; u < UF; ++u) {
            const int k = kc + u;
            const int pidx = (k + 1 + UF < SEQ) ? (k + 1 + UF) : (SEQ - 1);
            tick<true>(k, s, xbuf[u], xq + (size_t)pidx * BATCH * 4, out);
        }
    }
}

extern "C" void kernel_launch(void* const* d_in, const int* in_sizes, int n_in,
                              void* d_out, int out_size) {
    const float* x     = (const float*)d_in[0];
    const float* w_ih  = (const float*)d_in[1];
    const float* w_hh  = (const float*)d_in[2];
    const float* b_ih  = (const float*)d_in[3];
    const float* b_hh  = (const float*)d_in[4];
    const float* reg_w = (const float*)d_in[5];
    const float* reg_b = (const float*)d_in[6];
    float* out = (float*)d_out;

    // One warp per batch element; 1024 single-warp blocks spread over 148 SMs.
    lstm_reg_kernel<<<1024, 32>>>(x, w_ih, w_hh, b_ih, b_hh, reg_w, reg_b, out);
}

// round 6
// speedup vs baseline: 1.0902x; 1.0902x over previous
#include <cuda_runtime.h>

#define SEQ 2048
#define BATCH 1024
#define UF2 4
#define MASK 0xFFFFFFFFu

typedef unsigned long long ull;

__device__ __forceinline__ float tanh_ap(float x) {
    float y;
    asm("tanh.approx.f32 %0, %1;" : "=f"(y) : "f"(x));
    return y;
}
__device__ __forceinline__ ull pk(float lo, float hi) {
    ull r;
    asm("mov.b64 %0, {%1, %2};" : "=l"(r) : "f"(lo), "f"(hi));
    return r;
}
__device__ __forceinline__ void upk(float& lo, float& hi, ull v) {
    asm("mov.b64 {%0, %1}, %2;" : "=f"(lo), "=f"(hi) : "l"(v));
}
__device__ __forceinline__ ull fma2(ull a, ull b, ull c) {
    ull d;
    asm("fma.rn.f32x2 %0, %1, %2, %3;" : "=l"(d) : "l"(a), "l"(b), "l"(c));
    return d;
}
__device__ __forceinline__ void store_pred(int flag, float* p, float v) {
    asm volatile(
        "{\n\t.reg .pred %%pp;\n\t"
        "setp.ne.s32 %%pp, %0, 0;\n\t"
        "@%%pp st.global.f32 [%1], %2;\n\t}"
        :: "r"(flag), "l"(p), "f"(v));
}

struct LaneState {
    ull wi_if[4], wi_go[4], wh_if[4], wh_go[4];  // packed (i,f)/(g,o), pre-scaled
    ull b_if, b_go;
    float hA, hB, c2;     // layer lanes: h(t0),h(t1) as 2h, c2=2c. feeder: x even/odd.
    float rw0, rw1, rw2, rw3, rb;
    int l, bh, bi, b;
    int isfeed, flagA_base, flagB_base;
};

// One LSTM cell sub-step (identical math to the R4 kernel, which passed).
__device__ __forceinline__ void substep(
    const LaneState& s,
    float iv0, float iv1, float iv2, float iv3,
    float hv0, float hv1, float hv2, float hv3,
    float c2_in, float& nc2, float& nh)
{
    const ull dv_i0 = pk(iv0, iv0), dv_i1 = pk(iv1, iv1);
    const ull dv_i2 = pk(iv2, iv2), dv_i3 = pk(iv3, iv3);
    const ull dv_h0 = pk(hv0, hv0), dv_h1 = pk(hv1, hv1);
    const ull dv_h2 = pk(hv2, hv2), dv_h3 = pk(hv3, hv3);

    ull acc_if = s.b_if, acc_go = s.b_go;
    acc_if = fma2(s.wi_if[0], dv_i0, acc_if); acc_go = fma2(s.wi_go[0], dv_i0, acc_go);
    acc_if = fma2(s.wi_if[1], dv_i1, acc_if); acc_go = fma2(s.wi_go[1], dv_i1, acc_go);
    acc_if = fma2(s.wi_if[2], dv_i2, acc_if); acc_go = fma2(s.wi_go[2], dv_i2, acc_go);
    acc_if = fma2(s.wi_if[3], dv_i3, acc_if); acc_go = fma2(s.wi_go[3], dv_i3, acc_go);
    acc_if = fma2(s.wh_if[0], dv_h0, acc_if); acc_go = fma2(s.wh_go[0], dv_h0, acc_go);
    acc_if = fma2(s.wh_if[1], dv_h1, acc_if); acc_go = fma2(s.wh_go[1], dv_h1, acc_go);
    acc_if = fma2(s.wh_if[2], dv_h2, acc_if); acc_go = fma2(s.wh_go[2], dv_h2, acc_go);
    acc_if = fma2(s.wh_if[3], dv_h3, acc_if); acc_go = fma2(s.wh_go[3], dv_h3, acc_go);

    float gi, gf, gg, go;
    upk(gi, gf, acc_if);
    upk(gg, go, acc_go);

    const float ti = tanh_ap(gi);   // tanh(0.5*pre_i)
    const float tf = tanh_ap(gf);
    const float cc = tanh_ap(gg);   // tanh(pre_g)
    const float to = tanh_ap(go);

    // c2 = 2c: u = tf*c2+c2, v = ti*cc+cc; c2_new = 0.5u + v
    const ull uv = fma2(pk(tf, ti), pk(c2_in, cc), pk(c2_in, cc));
    float u, v;
    upk(u, v, uv);
    nc2 = fmaf(0.5f, u, v);
    const float th = tanh_ap(0.5f * nc2);
    nh = fmaf(to, th, th);          // 2*h_new
}

// Tick k: layer l processes timesteps t0=2(k-l), t1=t0+1. Feeder group 6 holds
// (x_even, x_odd) in (hA,hB); head group 7 (bi=20) computes/stores the linear head.
template<bool Guarded>
__device__ __forceinline__ void tick(int k, LaneState& s,
                                     float& xslotA, float& xslotB,
                                     const float* __restrict__ xq,
                                     float* __restrict__ out)
{
    const float hv0 = __shfl_sync(MASK, s.hB, s.bh + 0);
    const float hv1 = __shfl_sync(MASK, s.hB, s.bh + 1);
    const float hv2 = __shfl_sync(MASK, s.hB, s.bh + 2);
    const float hv3 = __shfl_sync(MASK, s.hB, s.bh + 3);
    const float ivA0 = __shfl_sync(MASK, s.hA, s.bi + 0);
    const float ivA1 = __shfl_sync(MASK, s.hA, s.bi + 1);
    const float ivA2 = __shfl_sync(MASK, s.hA, s.bi + 2);
    const float ivA3 = __shfl_sync(MASK, s.hA, s.bi + 3);
    const float ivB0 = __shfl_sync(MASK, s.hB, s.bi + 0);
    const float ivB1 = __shfl_sync(MASK, s.hB, s.bi + 1);
    const float ivB2 = __shfl_sync(MASK, s.hB, s.bi + 2);
    const float ivB3 = __shfl_sync(MASK, s.hB, s.bi + 3);

    // Head (group 7 reads layer-5 pairs via iv). Lane 28 stores t0, lane 29 t1.
    {
        float yA = s.rb, yB = s.rb;
        yA = fmaf(s.rw0, ivA0, yA); yB = fmaf(s.rw0, ivB0, yB);
        yA = fmaf(s.rw1, ivA1, yA); yB = fmaf(s.rw1, ivB1, yB);
        yA = fmaf(s.rw2, ivA2, yA); yB = fmaf(s.rw2, ivB2, yB);
        yA = fmaf(s.rw3, ivA3, yA); yB = fmaf(s.rw3, ivB3, yB);
        const int kh = k - 6;
        const int hok = Guarded ? ((unsigned)kh <= 1023) : 1;
        const int t0 = Guarded ? ((kh < 0 ? 0 : (kh > 1023 ? 1023 : kh)) * 2) : kh * 2;
        store_pred(s.flagA_base & hok, out + (size_t)t0 * BATCH + s.b, yA);
        store_pred(s.flagB_base & hok, out + (size_t)(t0 + 1) * BATCH + s.b, yB);
    }

    float ncA, nhA;
    substep(s, ivA0, ivA1, ivA2, ivA3, hv0, hv1, hv2, hv3, s.c2, ncA, nhA);

    // Mid-tick exchange of step-A h within own group (full warp participates).
    const float hvB0 = __shfl_sync(MASK, nhA, s.bh + 0);
    const float hvB1 = __shfl_sync(MASK, nhA, s.bh + 1);
    const float hvB2 = __shfl_sync(MASK, nhA, s.bh + 2);
    const float hvB3 = __shfl_sync(MASK, nhA, s.bh + 3);

    float ncB, nhB;
    substep(s, ivB0, ivB1, ivB2, ivB3, hvB0, hvB1, hvB2, hvB3, ncA, ncB, nhB);

    // Feeder refill: x for tick k+1 consumed now; prefetch for tick k+1+UF2.
    const float xA = xslotA, xB = xslotB;
    {
        int tp = 2 * (k + 1 + UF2);
        int tpA = tp, tpB = tp + 1;
        if (Guarded) { tpA = tpA > 2046 ? 2046 : tpA; tpB = tpB > 2047 ? 2047 : tpB; }
        xslotA = __ldg(xq + (size_t)tpA * BATCH * 4);
        xslotB = __ldg(xq + (size_t)tpB * BATCH * 4);
    }

    const int valid = Guarded ? ((unsigned)(k - s.l) <= 1023) : 1;
    const float hA2 = valid ? nhA : s.hA;
    const float hB2 = valid ? nhB : s.hB;
    const float c22 = valid ? ncB : s.c2;
    s.hA = s.isfeed ? xA : hA2;
    s.hB = s.isfeed ? xB : hB2;
    s.c2 = s.isfeed ? s.c2 : c22;
}

__global__ __launch_bounds__(32) void lstm_reg_kernel(
    const float* __restrict__ x,      // [S, B, 4]
    const float* __restrict__ w_ih,   // [6, 16, 4]
    const float* __restrict__ w_hh,   // [6, 16, 4]
    const float* __restrict__ b_ih,   // [6, 16]
    const float* __restrict__ b_hh,   // [6, 16]
    const float* __restrict__ reg_w,  // [1, 4]
    const float* __restrict__ reg_b,  // [1]
    float* __restrict__ out)          // [S, B, 1]
{
    const int lane = threadIdx.x & 31;

    LaneState s;
    s.b = blockIdx.x;
    s.l = lane >> 2;                  // 0..5 layers, 6 feeder, 7 head
    const int j = lane & 3;
    s.bh = s.l * 4;
    s.bi = (s.l == 0) ? 24 : ((s.l == 7) ? 20 : (s.l - 1) * 4);
    s.isfeed = (s.l == 6);
    s.flagA_base = (lane == 28);
    s.flagB_base = (lane == 29);

    float wi[4][4], wh[4][4], bb[4];
#pragma unroll
    for (int g = 0; g < 4; ++g) {
#pragma unroll
        for (int i = 0; i < 4; ++i) { wi[g][i] = 0.f; wh[g][i] = 0.f; }
        bb[g] = 0.f;
    }
    if (s.l < 6) {
#pragma unroll
        for (int g = 0; g < 4; ++g) {
            const int row = s.l * 16 + g * 4 + j;       // gate order i,f,g,o
            const float gsc = (g == 2) ? 1.0f : 0.5f;   // sigmoid-as-tanh fold
            const float isc = (s.l == 0) ? 1.0f : 0.5f; // input is 2h for layers>0
#pragma unroll
            for (int i = 0; i < 4; ++i) {
                wi[g][i] = w_ih[row * 4 + i] * gsc * isc;
                wh[g][i] = w_hh[row * 4 + i] * gsc * 0.5f;
            }
            bb[g] = (b_ih[row] + b_hh[row]) * gsc;
        }
    }
#pragma unroll
    for (int m = 0; m < 4; ++m) {
        s.wi_if[m] = pk(wi[0][m], wi[1][m]);
        s.wi_go[m] = pk(wi[2][m], wi[3][m]);
        s.wh_if[m] = pk(wh[0][m], wh[1][m]);
        s.wh_go[m] = pk(wh[2][m], wh[3][m]);
    }
    s.b_if = pk(bb[0], bb[1]);
    s.b_go = pk(bb[2], bb[3]);

    s.rw0 = reg_w[0] * 0.5f; s.rw1 = reg_w[1] * 0.5f;
    s.rw2 = reg_w[2] * 0.5f; s.rw3 = reg_w[3] * 0.5f;
    s.rb  = reg_b[0];

    s.hA = 0.f; s.hB = 0.f; s.c2 = 0.f;
    const float* xq = x + (size_t)s.b * 4 + j;
    if (s.isfeed) {
        s.hA = xq[0];
        s.hB = xq[(size_t)BATCH * 4];
    }

    // Prefetch ring: slot u (tick k ≡ u mod UF2) holds x(2(k+1)), x(2(k+1)+1).
    float xbufA[UF2], xbufB[UF2];
#pragma unroll
    for (int u = 0; u < UF2; ++u) {
        xbufA[u] = xq[(size_t)(2 * (u + 1)) * BATCH * 4];
        xbufB[u] = xq[(size_t)(2 * (u + 1) + 1) * BATCH * 4];
    }

    // ---- fill: ticks 0..7 (guarded) ----
#pragma unroll
    for (int u = 0; u < 8; ++u)
        tick<true>(u, s, xbufA[u & 3], xbufB[u & 3], xq, out);

    // ---- main: ticks 8..1015 unguarded, chunks of UF2 ----
#pragma unroll 1
    for (int kc = 8; kc < 1016; kc += UF2) {
#pragma unroll
        for (int u = 0; u < UF2; ++u)
            tick<false>(kc + u, s, xbufA[u], xbufB[u], xq, out);
    }

    // ---- drain: ticks 1016..1029 (guarded) ----
#pragma unroll 1
    for (int kc = 1016; kc < 1016 + 16; kc += UF2) {
#pragma unroll
        for (int u = 0; u < UF2; ++u) {
            const int k = kc + u;
            if (k < 1030)
                tick<true>(k, s, xbufA[u], xbufB[u], xq, out);
        }
    }
}

extern "C" void kernel_launch(void* const* d_in, const int* in_sizes, int n_in,
                              void* d_out, int out_size) {
    const float* x     = (const float*)d_in[0];
    const float* w_ih  = (const float*)d_in[1];
    const float* w_hh  = (const float*)d_in[2];
    const float* b_ih  = (const float*)d_in[3];
    const float* b_hh  = (const float*)d_in[4];
    const float* reg_w = (const float*)d_in[5];
    const float* reg_b = (const float*)d_in[6];
    float* out = (float*)d_out;

    lstm_reg_kernel<<<1024, 32>>>(x, w_ih, w_hh, b_ih, b_hh, reg_w, reg_b, out);
}